// round 16
// baseline (speedup 1.0000x reference)
#include <cuda_runtime.h>

// PIANO_EnergyV on (2,160,160,160) fp32, h=1.
// Round 13: smem-tiled interior kernel. Block = (4x,4y,32z) tile, 128 threads.
//  Phase 1: cp.async bulk-stage all 248 needed field rows (44-float z windows)
//           into 43.6KB static smem — one latency exposure, huge MLP.
//  Phase 2: compute from smem with the proven round-8 group formulas.
// Boundary frame handled by the scalar global-memory path in the same kernel.

#define NN 160
#define SXg (NN*NN)
#define SYg (NN)

#define W   44                 // staged window floats per row (z0g-4 .. z0g+39)
#define CH  11                 // 16B chunks per row
#define ZT  32                 // z-tile
#define NZT 5                  // 160/32
#define NINTB (40*40*NZT)      // 8000 interior blocks per batch
#define NBND (2*NN + 2*(NN-2)) // 636 boundary row-blocks per batch

// smem layout offsets (in floats)
#define OFFC    0
#define OFFDXY  (36*W)
#define OFFDXX  (72*W)
#define OFFDXZ  (96*W)
#define OFFVX   (120*W)
#define OFFDYY  (144*W)
#define OFFDYZ  (168*W)
#define OFFVY   (192*W)
#define OFFDZZ  (216*W)
#define OFFVZ   (232*W)
#define SMTOT   (248*W)        // 10912 floats = 43648 bytes

// row base (float index into sm) helpers
#define ROW6(off, xi, yi) ((off) + ((xi)*6 + (yi))*W)   // 6x6 grids (C, Dxy)
#define ROWX(off, xi, yi) ((off) + ((xi)*4 + (yi))*W)   // 6x4 grids (x-halo)
#define ROWY(off, xi, yi) ((off) + ((xi)*6 + (yi))*W)   // 4x6 grids (y-halo)
#define ROWZ(off, xi, yi) ((off) + ((xi)*4 + (yi))*W)   // 4x4 grids (center)

// smem row reads: dst[k] holds value at z = z0 - 1 + k; window base wb = 4*zc.
#define SMID4(dst, rbase) do { \
    const float4 _q = *(const float4*)(sm + (rbase) + wb + 4); \
    dst[1] = _q.x; dst[2] = _q.y; dst[3] = _q.z; dst[4] = _q.w; } while (0)
#define SFULL6(dst, rbase) do { \
    SMID4(dst, rbase); \
    dst[0] = sm[(rbase) + wb + 3]; \
    dst[5] = sm[(rbase) + wb + 8]; } while (0)

__device__ __forceinline__ void boundary_path(
    int idx, int b,
    const float* __restrict__ C,
    const float* __restrict__ Vx,
    const float* __restrict__ Vy,
    const float* __restrict__ Vz,
    const float* __restrict__ Dxx,
    const float* __restrict__ Dxy,
    const float* __restrict__ Dxz,
    const float* __restrict__ Dyy,
    const float* __restrict__ Dyz,
    const float* __restrict__ Dzz,
    float* __restrict__ out)
{
    int x, y;
    if (idx < 2 * NN) {
        x = (idx < NN) ? 0 : NN - 1;
        y = idx % NN;
    } else {
        int r = idx - 2 * NN;
        x = 1 + (r >> 1);
        y = (r & 1) ? NN - 1 : 0;
    }
    for (int z = threadIdx.x; z < NN; z += 128) {
        const int i = ((b * NN + x) * NN + y) * NN + z;

        const int dxm = (x > 0)      ? -SXg : 0;
        const int dxp = (x < NN - 1) ?  SXg : 0;
        const float wx = (x > 0 && x < NN - 1) ? 0.5f : 1.0f;
        const int dym = (y > 0)      ? -SYg : 0;
        const int dyp = (y < NN - 1) ?  SYg : 0;
        const float wy = (y > 0 && y < NN - 1) ? 0.5f : 1.0f;
        const int dzm = (z > 0)      ? -1 : 0;
        const int dzp = (z < NN - 1) ?  1 : 0;
        const float wz = (z > 0 && z < NN - 1) ? 0.5f : 1.0f;

        const int fx0 = (x == NN - 1) ? -SXg : 0;  const int fx1 = fx0 + SXg;
        const int fy0 = (y == NN - 1) ? -SYg : 0;  const int fy1 = fy0 + SYg;
        const int fz0 = (z == NN - 1) ? -1   : 0;  const int fz1 = fz0 + 1;

        const int bx1 = (x == 0) ? SXg : 0;  const int bx0 = bx1 - SXg;
        const int by1 = (y == 0) ? SYg : 0;  const int by0 = by1 - SYg;
        const int bz1 = (z == 0) ? 1   : 0;  const int bz0 = bz1 - 1;

        const float cXC = (C[i + dxp] - C[i + dxm]) * wx;
        const float cYC = (C[i + dyp] - C[i + dym]) * wy;
        const float cZC = (C[i + dzp] - C[i + dzm]) * wz;

        const float gx = (Dxx[i + dxp] - Dxx[i + dxm]) * wx
                       + (Dxy[i + dyp] - Dxy[i + dym]) * wy
                       + (Dxz[i + dzp] - Dxz[i + dzm]) * wz;
        const float gy = (Dxy[i + dxp] - Dxy[i + dxm]) * wx
                       + (Dyy[i + dyp] - Dyy[i + dym]) * wy
                       + (Dyz[i + dzp] - Dyz[i + dzm]) * wz;
        const float gz = (Dxz[i + dxp] - Dxz[i + dxm]) * wx
                       + (Dyz[i + dyp] - Dyz[i + dym]) * wy
                       + (Dzz[i + dzp] - Dzz[i + dzm]) * wz;

        const float sxx = (x == NN - 1) ? 0.0f
                        : (C[i + bx1 + SXg] - 2.0f * C[i + bx1] + C[i + bx1 - SXg]);
        const float syy = (y == NN - 1) ? 0.0f
                        : (C[i + by1 + SYg] - 2.0f * C[i + by1] + C[i + by1 - SYg]);
        const float szz = (z == NN - 1) ? 0.0f
                        : (C[i + bz1 + 1]   - 2.0f * C[i + bz1] + C[i + bz1 - 1]);

        #define MIX(bA1, bA0, fB1, fB0) \
            ((C[i + (bA1) + (fB1)] - C[i + (bA1) + (fB0)]) - \
             (C[i + (bA0) + (fB1)] - C[i + (bA0) + (fB0)]))
        const float mXY = MIX(bx1, bx0, fy1, fy0);
        const float mYX = MIX(by1, by0, fx1, fx0);
        const float mYZ = MIX(by1, by0, fz1, fz0);
        const float mZY = MIX(bz1, bz0, fy1, fy0);
        const float mZX = MIX(bz1, bz0, fx1, fx0);
        const float mXZ = MIX(bx1, bx0, fz1, fz0);
        #undef MIX

        const float diff = gx * cXC + gy * cYC + gz * cZC
                         + Dxx[i] * sxx + Dyy[i] * syy + Dzz[i] * szz
                         + Dxy[i] * (mXY + mYX)
                         + Dyz[i] * (mYZ + mZY)
                         + Dxz[i] * (mZX + mXZ);

        const float vx = Vx[i], vy = Vy[i], vz = Vz[i];
        const float bXC = C[i + bx1] - C[i + bx0];
        const float fXC = C[i + fx1] - C[i + fx0];
        const float bYC = C[i + by1] - C[i + by0];
        const float fYC = C[i + fy1] - C[i + fy0];
        const float bZC = C[i + bz1] - C[i + bz0];
        const float fZC = C[i + fz1] - C[i + fz0];
        const float Cux = (vx > 0.0f) ? bXC : fXC;
        const float Cuy = (vy > 0.0f) ? bYC : fYC;
        const float Cuz = (vz > 0.0f) ? bZC : fZC;

        const float divV = (Vx[i + dxp] - Vx[i + dxm]) * wx
                         + (Vy[i + dyp] - Vy[i + dym]) * wy
                         + (Vz[i + dzp] - Vz[i + dzm]) * wz;

        const float adv = -(vx * Cux + vy * Cuy + vz * Cuz) - C[i] * divV;
        out[i] = diff + adv;
    }
}

__global__ __launch_bounds__(128, 4)
void piano_all(
    const float* __restrict__ C_,
    const float* __restrict__ Vx_,
    const float* __restrict__ Vy_,
    const float* __restrict__ Vz_,
    const float* __restrict__ Dxx_,
    const float* __restrict__ Dxy_,
    const float* __restrict__ Dxz_,
    const float* __restrict__ Dyy_,
    const float* __restrict__ Dyz_,
    const float* __restrict__ Dzz_,
    float* __restrict__ out)
{
    __shared__ float sm[SMTOT];
    const int bi = blockIdx.x;
    const int b  = blockIdx.y;

    if (bi >= NINTB) {
        boundary_path(bi - NINTB, b, C_, Vx_, Vy_, Vz_,
                      Dxx_, Dxy_, Dxz_, Dyy_, Dyz_, Dzz_, out);
        return;
    }

    const int tz = bi % NZT;
    const int r2 = bi / NZT;
    const int ty = r2 % 40;
    const int tx = r2 / 40;
    const int x0 = 1 + 4 * tx;
    const int y0 = 1 + 4 * ty;
    const int z0g = ZT * tz;
    const int tid = threadIdx.x;

    unsigned smbase;
    asm("{ .reg .u64 t; cvta.to.shared.u64 t, %1; cvt.u32.u64 %0, t; }"
        : "=r"(smbase) : "l"(sm));

    // ---------------- Phase 1: cp.async staging ----------------
    #define STAGE(PTR, NX, NY, XOFF, YOFF, OFF) do { \
        const int total = (NX) * (NY) * CH; \
        for (int j = tid; j < total; j += 128) { \
            const int r = j / CH, c = j % CH; \
            const int xi = r / (NY), yi = r % (NY); \
            int gx = x0 + (XOFF) + xi; gx = min(max(gx, 0), NN - 1); \
            int gy = y0 + (YOFF) + yi; gy = min(max(gy, 0), NN - 1); \
            int zs = z0g - 4 + 4 * c;  zs = min(max(zs, 0), NN - 4); \
            const float* src = (PTR) + (((b * NN + gx) * NN + gy) * NN + zs); \
            const unsigned dst = smbase + (unsigned)(((OFF) + r * W + 4 * c) * 4); \
            asm volatile("cp.async.ca.shared.global [%0], [%1], 16;" \
                         :: "r"(dst), "l"(src)); \
        } } while (0)

    STAGE(C_,   6, 6, -1, -1, OFFC);
    STAGE(Dxy_, 6, 6, -1, -1, OFFDXY);
    STAGE(Dxx_, 6, 4, -1,  0, OFFDXX);
    STAGE(Dxz_, 6, 4, -1,  0, OFFDXZ);
    STAGE(Vx_,  6, 4, -1,  0, OFFVX);
    STAGE(Dyy_, 4, 6,  0, -1, OFFDYY);
    STAGE(Dyz_, 4, 6,  0, -1, OFFDYZ);
    STAGE(Vy_,  4, 6,  0, -1, OFFVY);
    STAGE(Dzz_, 4, 4,  0,  0, OFFDZZ);
    STAGE(Vz_,  4, 4,  0,  0, OFFVZ);
    #undef STAGE

    asm volatile("cp.async.commit_group;" ::: "memory");
    asm volatile("cp.async.wait_group 0;" ::: "memory");
    __syncthreads();

    // ---------------- Phase 2: compute from smem ----------------
    const int col = tid >> 3;         // 16 xy-columns
    const int zc  = tid & 7;          // 8 z-chunks of 4
    const int cx  = col >> 2;
    const int cy  = col & 3;
    const int x   = x0 + cx;
    const int y   = y0 + cy;
    const int z0  = z0g + 4 * zc;
    const int wb  = 4 * zc;
    const bool valid = (x <= NN - 2) && (y <= NN - 2);
    const bool zlo0 = (z0 == 0);
    const bool zhi3 = (z0 == NN - 4);

    // C rows (live throughout)
    float c00[6], cxm[6], cxp[6], cym[6], cyp[6];
    SFULL6(c00, ROW6(OFFC, cx + 1, cy + 1));
    SFULL6(cxm, ROW6(OFFC, cx,     cy + 1));
    SFULL6(cxp, ROW6(OFFC, cx + 2, cy + 1));
    SFULL6(cym, ROW6(OFFC, cx + 1, cy));
    SFULL6(cyp, ROW6(OFFC, cx + 1, cy + 2));

    #define CXCk(k) ((cxp[k] - cxm[k]) * 0.5f)
    #define CYCk(k) ((cyp[k] - cym[k]) * 0.5f)
    #define CZCk(k, zlo, zhi) \
        ((zlo) ? (c00[(k)+1] - c00[k]) \
       : (zhi) ? (c00[k]   - c00[(k)-1]) \
               : (c00[(k)+1] - c00[(k)-1]) * 0.5f)

    float res[4];

    // ==== G1: Dxx + Dyy ====
    {
        float axc[6], axm[6], axp[6], ayc[6], aym[6], ayp[6];
        SMID4(axc, ROWX(OFFDXX, cx + 1, cy));
        SMID4(axm, ROWX(OFFDXX, cx,     cy));
        SMID4(axp, ROWX(OFFDXX, cx + 2, cy));
        SMID4(ayc, ROWY(OFFDYY, cx, cy + 1));
        SMID4(aym, ROWY(OFFDYY, cx, cy));
        SMID4(ayp, ROWY(OFFDYY, cx, cy + 2));
        #pragma unroll
        for (int e = 0; e < 4; e++) { const int k = e + 1;
            float sxx = cxp[k] - 2.0f * c00[k] + cxm[k];
            float syy = cyp[k] - 2.0f * c00[k] + cym[k];
            res[e] = (axp[k] - axm[k]) * 0.5f * CXCk(k) + axc[k] * sxx
                   + (ayp[k] - aym[k]) * 0.5f * CYCk(k) + ayc[k] * syy;
        }
    }
    // ==== G2: Dzz ====
    {
        float azc[6];
        SFULL6(azc, ROWZ(OFFDZZ, cx, cy));
        #pragma unroll
        for (int e = 0; e < 4; e++) { const int k = e + 1;
            const bool zlo = (e == 0) && zlo0;
            const bool zhi = (e == 3) && zhi3;
            float cz  = zlo ? (azc[k+1] - azc[k])
                      : zhi ? (azc[k]   - azc[k-1])
                            : (azc[k+1] - azc[k-1]) * 0.5f;
            float szz = zhi ? 0.0f
                      : zlo ? (c00[k+2] - 2.0f * c00[k+1] + c00[k])
                            : (c00[k+1] - 2.0f * c00[k]   + c00[k-1]);
            res[e] += cz * CZCk(k, zlo, zhi) + azc[k] * szz;
        }
    }
    // ==== G3 + G4: Dxy with xy-corner C rows ====
    {
        float cq1[6], cq2[6], dc[6], dxm2[6], dxp2[6], dym2[6], dyp2[6];
        SMID4(cq1, ROW6(OFFC, cx,     cy + 2));   // (x-1, y+1)
        SMID4(cq2, ROW6(OFFC, cx + 2, cy));       // (x+1, y-1)
        SMID4(dc,   ROW6(OFFDXY, cx + 1, cy + 1));
        SMID4(dxm2, ROW6(OFFDXY, cx,     cy + 1));
        SMID4(dxp2, ROW6(OFFDXY, cx + 2, cy + 1));
        SMID4(dym2, ROW6(OFFDXY, cx + 1, cy));
        SMID4(dyp2, ROW6(OFFDXY, cx + 1, cy + 2));
        #pragma unroll
        for (int e = 0; e < 4; e++) { const int k = e + 1;
            float mXY = (cyp[k] - c00[k]) - (cq1[k] - cxm[k]);
            float mYX = (cxp[k] - c00[k]) - (cq2[k] - cym[k]);
            res[e] += (dxp2[k] - dxm2[k]) * 0.5f * CYCk(k)
                    + (dyp2[k] - dym2[k]) * 0.5f * CXCk(k)
                    + dc[k] * (mXY + mYX);
        }
    }
    // ==== G5: Dxz ====
    {
        float ec[6], em[6], ep[6];
        SFULL6(ec, ROWX(OFFDXZ, cx + 1, cy));
        SMID4 (em, ROWX(OFFDXZ, cx,     cy));
        SMID4 (ep, ROWX(OFFDXZ, cx + 2, cy));
        #pragma unroll
        for (int e = 0; e < 4; e++) { const int k = e + 1;
            const bool zlo = (e == 0) && zlo0;
            const bool zhi = (e == 3) && zhi3;
            float czE = zlo ? (ec[k+1] - ec[k])
                      : zhi ? (ec[k]   - ec[k-1])
                            : (ec[k+1] - ec[k-1]) * 0.5f;
            float czf0 = zhi ? (c00[k] - c00[k-1]) : (c00[k+1] - c00[k]);
            float czfx = zhi ? (cxm[k] - cxm[k-1]) : (cxm[k+1] - cxm[k]);
            float mXZ = czf0 - czfx;
            float mZX = zlo ? ((cxp[k+1] - c00[k+1]) - (cxp[k]   - c00[k]))
                            : ((cxp[k]   - c00[k])   - (cxp[k-1] - c00[k-1]));
            res[e] += czE * CXCk(k) + (ep[k] - em[k]) * 0.5f * CZCk(k, zlo, zhi)
                    + ec[k] * (mXZ + mZX);
        }
    }
    // ==== G6: Dyz ====
    {
        float fc[6], fm[6], fp[6];
        SFULL6(fc, ROWY(OFFDYZ, cx, cy + 1));
        SMID4 (fm, ROWY(OFFDYZ, cx, cy));
        SMID4 (fp, ROWY(OFFDYZ, cx, cy + 2));
        #pragma unroll
        for (int e = 0; e < 4; e++) { const int k = e + 1;
            const bool zlo = (e == 0) && zlo0;
            const bool zhi = (e == 3) && zhi3;
            float czF = zlo ? (fc[k+1] - fc[k])
                      : zhi ? (fc[k]   - fc[k-1])
                            : (fc[k+1] - fc[k-1]) * 0.5f;
            float czf0 = zhi ? (c00[k] - c00[k-1]) : (c00[k+1] - c00[k]);
            float czfy = zhi ? (cym[k] - cym[k-1]) : (cym[k+1] - cym[k]);
            float mYZ = czf0 - czfy;
            float mZY = zlo ? ((cyp[k+1] - c00[k+1]) - (cyp[k]   - c00[k]))
                            : ((cyp[k]   - c00[k])   - (cyp[k-1] - c00[k-1]));
            res[e] += czF * CYCk(k) + (fp[k] - fm[k]) * 0.5f * CZCk(k, zlo, zhi)
                    + fc[k] * (mYZ + mZY);
        }
    }
    // ==== G7: Vx + Vy ====
    {
        float vxc[6], vxm[6], vxp[6], vyc[6], vym[6], vyp[6];
        SMID4(vxc, ROWX(OFFVX, cx + 1, cy));
        SMID4(vxm, ROWX(OFFVX, cx,     cy));
        SMID4(vxp, ROWX(OFFVX, cx + 2, cy));
        SMID4(vyc, ROWY(OFFVY, cx, cy + 1));
        SMID4(vym, ROWY(OFFVY, cx, cy));
        SMID4(vyp, ROWY(OFFVY, cx, cy + 2));
        #pragma unroll
        for (int e = 0; e < 4; e++) { const int k = e + 1;
            float vx = vxc[k], vy = vyc[k];
            float cux = (vx > 0.0f) ? (c00[k] - cxm[k]) : (cxp[k] - c00[k]);
            float cuy = (vy > 0.0f) ? (c00[k] - cym[k]) : (cyp[k] - c00[k]);
            res[e] += -(vx * cux + vy * cuy)
                    - c00[k] * ((vxp[k] - vxm[k]) * 0.5f + (vyp[k] - vym[k]) * 0.5f);
        }
    }
    // ==== G8: Vz ====
    {
        float vzc[6];
        SFULL6(vzc, ROWZ(OFFVZ, cx, cy));
        #pragma unroll
        for (int e = 0; e < 4; e++) { const int k = e + 1;
            const bool zlo = (e == 0) && zlo0;
            const bool zhi = (e == 3) && zhi3;
            float vz  = vzc[k];
            float cbz = zlo ? (c00[k+1] - c00[k]) : (c00[k] - c00[k-1]);
            float cfz = zhi ? (c00[k] - c00[k-1]) : (c00[k+1] - c00[k]);
            float cuz = (vz > 0.0f) ? cbz : cfz;
            float dvz = zlo ? (vzc[k+1] - vzc[k])
                      : zhi ? (vzc[k]   - vzc[k-1])
                            : (vzc[k+1] - vzc[k-1]) * 0.5f;
            res[e] += -vz * cuz - c00[k] * dvz;
        }
    }

    if (valid) {
        float4 o;
        o.x = res[0]; o.y = res[1]; o.z = res[2]; o.w = res[3];
        *reinterpret_cast<float4*>(out + ((b * NN + x) * NN + y) * NN + z0) = o;
    }
}

extern "C" void kernel_launch(void* const* d_in, const int* in_sizes, int n_in,
                              void* d_out, int out_size)
{
    const float* C   = (const float*)d_in[0];
    const float* Vx  = (const float*)d_in[1];
    const float* Vy  = (const float*)d_in[2];
    const float* Vz  = (const float*)d_in[3];
    const float* Dxx = (const float*)d_in[4];
    const float* Dxy = (const float*)d_in[5];
    const float* Dxz = (const float*)d_in[6];
    const float* Dyy = (const float*)d_in[7];
    const float* Dyz = (const float*)d_in[8];
    const float* Dzz = (const float*)d_in[9];
    float* out = (float*)d_out;

    dim3 grid(NINTB + NBND, 2);
    piano_all<<<grid, 128>>>(C, Vx, Vy, Vz, Dxx, Dxy, Dxz, Dyy, Dyz, Dzz, out);
}